// round 13
// baseline (speedup 1.0000x reference)
#include <cuda_runtime.h>
#include <cuda_bf16.h>
#include <math.h>

#define Bsz 512
#define Hd  1024
#define Od  512
#define KC  1536   // Od + Hd
#define G4  4096   // 4*Hd
#define KSPLIT 8   // logits split-K
#define GSPLIT 2   // gates split-K

// ---------------- scratch ----------------
__device__ __nv_bfloat16 g_Xh[Bsz * KC];      // [B][KC]: x cols 0..511, h cols 512..1535
__device__ __nv_bfloat16 g_Xl[Bsz * KC];
__device__ __nv_bfloat16 g_Wh[G4 * KC];       // gate-interleaved [4j+gate][k]
__device__ __nv_bfloat16 g_Wl[G4 * KC];
__device__ __nv_bfloat16 g_Woh[Od * Hd];
__device__ __nv_bfloat16 g_Wol[Od * Hd];
__device__ float g_c[Bsz * Hd];               // [b][j]
__device__ float g_bias[G4];                  // gate-interleaved
__device__ float g_gp[GSPLIT][Bsz * G4];      // gates split-K partials
__device__ float g_lp[KSPLIT][Bsz * Od];      // logits split-K partials

// ---------------- grid barrier (two-level; used ONLY in 128-block kernel) --
struct GBar { unsigned sub[16]; unsigned root; unsigned gen; };
__device__ GBar g_barB;                       // zero-init; counters return to 0 each use

template<int PER_SUB>
__device__ __forceinline__ void gridbar(GBar* B, int bid) {
    __syncthreads();
    if (threadIdx.x == 0) {
        volatile unsigned* genp = &B->gen;
        unsigned mygen = *genp;               // read BEFORE arriving
        __threadfence();                      // release this block's writes
        int s = bid & 15;
        if (atomicAdd(&B->sub[s], 1u) == (unsigned)(PER_SUB - 1)) {
            B->sub[s] = 0u;                   // reset for next use
            if (atomicAdd(&B->root, 1u) == 15u) {
                B->root = 0u;
                __threadfence();
                atomicAdd(&B->gen, 1u);       // release
            }
        }
        while (*genp == mygen) { __nanosleep(32); }
        __threadfence();                      // acquire peers' writes
    }
    __syncthreads();
}

__device__ __forceinline__ void split_bf16(float v, __nv_bfloat16& hi, __nv_bfloat16& lo) {
    hi = __float2bfloat16(v);
    lo = __float2bfloat16(v - __bfloat162float(hi));
}
__device__ __forceinline__ float sigm(float x) { return 1.0f / (1.0f + __expf(-x)); }
__device__ __forceinline__ float ftanh(float x) { return 1.0f - 2.0f / (__expf(2.0f * x) + 1.0f); }

// ---------------- prep -------------------
__global__ void prep_weights(const float* __restrict__ W_ih,
                             const float* __restrict__ W_hh,
                             const float* __restrict__ b_ih,
                             const float* __restrict__ b_hh,
                             const float* __restrict__ W_out) {
    int idx = blockIdx.x * blockDim.x + threadIdx.x;
    if (idx < G4 * KC) {
        int r = idx / KC;
        int k = idx - r * KC;
        int j = r >> 2, gate = r & 3;
        int orow = gate * Hd + j;
        float w = (k < Od) ? W_ih[orow * Od + k] : W_hh[orow * Hd + (k - Od)];
        __nv_bfloat16 hi, lo;
        split_bf16(w, hi, lo);
        g_Wh[idx] = hi;
        g_Wl[idx] = lo;
    }
    if (idx < G4) {
        int j = idx >> 2, gate = idx & 3;
        g_bias[idx] = b_ih[gate * Hd + j] + b_hh[gate * Hd + j];
    }
    if (idx < Od * Hd) {
        __nv_bfloat16 hi, lo;
        split_bf16(W_out[idx], hi, lo);
        g_Woh[idx] = hi;
        g_Wol[idx] = lo;
    }
}

__global__ void prep_state(const float* __restrict__ h0,
                           const float* __restrict__ c0) {
    int idx = blockIdx.x * blockDim.x + threadIdx.x;
    if (idx < Bsz * Hd) {
        int b = idx >> 10;
        int j = idx & (Hd - 1);
        __nv_bfloat16 hi, lo;
        split_bf16(h0[idx], hi, lo);
        g_Xh[b * KC + Od + j] = hi;
        g_Xl[b * KC + Od + j] = lo;
        g_c[idx] = c0[idx];
    }
    if (idx < Bsz * Od) {
        int b = idx >> 9;
        int k = idx & (Od - 1);
        g_Xh[b * KC + k] = __float2bfloat16(0.0f);
        g_Xl[b * KC + k] = __float2bfloat16(0.0f);
    }
}

// ---------------- asm helpers --------------------------------------------
#define SWZ(b) ((b) ^ (((b) >> 3) & 0x30))   // 64B-row XOR swizzle

#define CP_ASYNC16(dst, src) asm volatile("cp.async.cg.shared.global [%0], [%1], 16;\n" :: "r"(dst), "l"(src))
#define CP_COMMIT            asm volatile("cp.async.commit_group;\n")
#define CP_WAIT2             asm volatile("cp.async.wait_group 2;\n")
#define CP_WAIT1             asm volatile("cp.async.wait_group 1;\n")
#define CP_WAIT0             asm volatile("cp.async.wait_group 0;\n")

#define LDSM_X4(d0, d1, d2, d3, addr) \
    asm volatile("ldmatrix.sync.aligned.m8n8.x4.shared.b16 {%0,%1,%2,%3}, [%4];" \
                 : "=r"(d0), "=r"(d1), "=r"(d2), "=r"(d3) : "r"(addr))

#define MMA_BF16(acc, a, b) \
    asm volatile( \
        "mma.sync.aligned.m16n8k16.row.col.f32.bf16.bf16.f32 " \
        "{%0,%1,%2,%3}, {%4,%5,%6,%7}, {%8,%9}, {%0,%1,%2,%3};" \
        : "+f"((acc)[0]), "+f"((acc)[1]), "+f"((acc)[2]), "+f"((acc)[3]) \
        : "r"((a)[0]), "r"((a)[1]), "r"((a)[2]), "r"((a)[3]), \
          "r"((b)[0]), "r"((b)[1]))

#define STAGE_G 32768
#define SMEM_G  (3 * STAGE_G)    // 96 KB

// ==========================================================================
// gates GEMM, split-K=2: partial[kz][512,4096] = X[:,kz*768:+768] @ W^T.
// BM=BN=128, BK=32, 24 k-iters. grid (32, 4, 2) = 256 blocks, 2 CTAs/SM.
// No combine tail — partials only (combine happens in mid_step).
// ==========================================================================
#define NT_G 24
#define KHALF 768

__global__ __launch_bounds__(256, 2) void gates_mma() {
    extern __shared__ __align__(1024) unsigned char smg[];

    const int tid  = threadIdx.x;
    const int wid  = tid >> 5;
    const int lane = tid & 31;
    const int warp_m = wid >> 2;   // 0..1
    const int warp_n = wid & 3;    // 0..3
    const int bm = blockIdx.y * 128;
    const int bn = blockIdx.x * 128;
    const int kz = blockIdx.z;
    const int kb = kz * KHALF;

    const unsigned sbase = (unsigned)__cvta_generic_to_shared(smg);

    const int rA0 = tid >> 2;        // 0..63
    const int rA1 = rA0 + 64;
    const int kc  = tid & 3;
    const unsigned sOff0 = SWZ((unsigned)(rA0 * 64 + kc * 16));
    const unsigned sOff1 = SWZ((unsigned)(rA1 * 64 + kc * 16));

    float acc[4][4][4];
    #pragma unroll
    for (int i = 0; i < 4; i++)
        #pragma unroll
        for (int j = 0; j < 4; j++)
            #pragma unroll
            for (int q = 0; q < 4; q++) acc[i][j][q] = 0.0f;

    #define LOADG(I, BUF) do {                                                \
        int k0_ = kb + (I) * 32;                                              \
        unsigned s_ = sbase + (BUF) * STAGE_G;                                \
        size_t a0_ = (size_t)(bm + rA0) * KC + k0_ + kc * 8;                  \
        size_t a1_ = (size_t)(bm + rA1) * KC + k0_ + kc * 8;                  \
        size_t b0_ = (size_t)(bn + rA0) * KC + k0_ + kc * 8;                  \
        size_t b1_ = (size_t)(bn + rA1) * KC + k0_ + kc * 8;                  \
        CP_ASYNC16(s_ + sOff0,          g_Xh + a0_);                          \
        CP_ASYNC16(s_ + sOff1,          g_Xh + a1_);                          \
        CP_ASYNC16(s_ + 8192  + sOff0,  g_Xl + a0_);                          \
        CP_ASYNC16(s_ + 8192  + sOff1,  g_Xl + a1_);                          \
        CP_ASYNC16(s_ + 16384 + sOff0,  g_Wh + b0_);                          \
        CP_ASYNC16(s_ + 16384 + sOff1,  g_Wh + b1_);                          \
        CP_ASYNC16(s_ + 24576 + sOff0,  g_Wl + b0_);                          \
        CP_ASYNC16(s_ + 24576 + sOff1,  g_Wl + b1_);                          \
        CP_COMMIT;                                                            \
    } while (0)

    LOADG(0, 0);
    LOADG(1, 1);

    for (int it = 0; it < NT_G; it++) {
        const int buf = it % 3;
        if (it + 2 < NT_G) {
            LOADG(it + 2, (it + 2) % 3);
            CP_WAIT2;
        } else if (it + 1 < NT_G) {
            CP_WAIT1;
        } else {
            CP_WAIT0;
        }
        __syncthreads();

        const unsigned sb = sbase + buf * STAGE_G;

        #pragma unroll
        for (int kk = 0; kk < 2; kk++) {
            const unsigned ar  = (unsigned)(lane & 15);
            const unsigned ahk = (unsigned)(lane >> 4);
            unsigned ah[4][4], al[4][4];
            #pragma unroll
            for (int mf = 0; mf < 4; mf++) {
                unsigned byte = (warp_m * 64 + mf * 16 + ar) * 64 + kk * 32 + ahk * 16;
                unsigned sw = SWZ(byte);
                LDSM_X4(ah[mf][0], ah[mf][1], ah[mf][2], ah[mf][3], sb + sw);
                LDSM_X4(al[mf][0], al[mf][1], al[mf][2], al[mf][3], sb + 8192 + sw);
            }
            unsigned bh[4][2], bl[4][2];
            #pragma unroll
            for (int pr = 0; pr < 2; pr++) {
                unsigned n = warp_n * 32 + pr * 16 + (lane & 7) + ((lane >> 4) & 1) * 8;
                unsigned byte = n * 64 + kk * 32 + ((lane >> 3) & 1) * 16;
                unsigned sw = SWZ(byte);
                unsigned r0, r1, r2, r3;
                LDSM_X4(r0, r1, r2, r3, sb + 16384 + sw);
                bh[2 * pr][0] = r0;      bh[2 * pr][1] = r1;
                bh[2 * pr + 1][0] = r2;  bh[2 * pr + 1][1] = r3;
                LDSM_X4(r0, r1, r2, r3, sb + 24576 + sw);
                bl[2 * pr][0] = r0;      bl[2 * pr][1] = r1;
                bl[2 * pr + 1][0] = r2;  bl[2 * pr + 1][1] = r3;
            }
            #pragma unroll
            for (int mf = 0; mf < 4; mf++)
                #pragma unroll
                for (int nf = 0; nf < 4; nf++)
                    MMA_BF16(acc[mf][nf], ah[mf], bh[nf]);
            #pragma unroll
            for (int mf = 0; mf < 4; mf++)
                #pragma unroll
                for (int nf = 0; nf < 4; nf++)
                    MMA_BF16(acc[mf][nf], ah[mf], bl[nf]);
            #pragma unroll
            for (int mf = 0; mf < 4; mf++)
                #pragma unroll
                for (int nf = 0; nf < 4; nf++)
                    MMA_BF16(acc[mf][nf], al[mf], bh[nf]);
        }
        __syncthreads();
    }

    float* gp = g_gp[kz];
    #pragma unroll
    for (int mf = 0; mf < 4; mf++) {
        #pragma unroll
        for (int nf = 0; nf < 4; nf++) {
            int row = bm + warp_m * 64 + mf * 16 + (lane >> 2);
            int col = bn + warp_n * 32 + nf * 8 + (lane & 3) * 2;
            *(float2*)&gp[(size_t)row * G4 + col] = make_float2(acc[mf][nf][0], acc[mf][nf][1]);
            *(float2*)&gp[(size_t)(row + 8) * G4 + col] = make_float2(acc[mf][nf][2], acc[mf][nf][3]);
        }
    }
}

// ==========================================================================
// mid_step (128 blocks, 1 CTA/SM residency guaranteed):
//   phase C: distributed cell update (partial sum + bias + LSTM) -> h
//   gridbar
//   phase L: logits GEMM split-K=8 (NT=4 pipelined) -> g_lp
// ==========================================================================
#define NT_L 4

__global__ __launch_bounds__(256, 2) void mid_step() {
    extern __shared__ __align__(1024) unsigned char sml[];
    const unsigned sbase = (unsigned)__cvta_generic_to_shared(sml);
    const int bid  = blockIdx.x;
    const int tid  = threadIdx.x;
    const int wid  = tid >> 5;
    const int lane = tid & 31;
    const int warp_m = wid >> 2;
    const int warp_n = wid & 3;

    // ---- phase C: cell update ----
    {
        const float* p0 = g_gp[0];
        const float* p1 = g_gp[1];
        int base = bid * 256 + tid;            // 0..32767
        #pragma unroll
        for (int k = 0; k < 16; k++) {
            int g = base + k * 32768;          // 0..524287
            int b = g >> 10;
            int j = g & (Hd - 1);
            size_t gidx = (size_t)b * G4 + 4 * j;

            float4 a  = *(const float4*)&p0[gidx];
            float4 bb = *(const float4*)&p1[gidx];
            float4 bs = *(const float4*)&g_bias[4 * j];

            float gi = a.x + bb.x + bs.x;
            float gf = a.y + bb.y + bs.y;
            float gg = a.z + bb.z + bs.z;
            float go = a.w + bb.w + bs.w;

            float c  = g_c[g];
            float cn = sigm(gf) * c + sigm(gi) * ftanh(gg);
            g_c[g] = cn;
            float hn = sigm(go) * ftanh(cn);

            __nv_bfloat16 hi, lo;
            split_bf16(hn, hi, lo);
            g_Xh[b * KC + Od + j] = hi;
            g_Xl[b * KC + Od + j] = lo;
        }
    }
    gridbar<8>(&g_barB, bid);                  // 128 blocks: 16 subgroups x 8

    // ---- phase L: logits GEMM split-K=8 ----
    {
        const int kz  = bid >> 4;              // 0..7
        const int rem = bid & 15;
        const int bm  = (rem >> 2) * 128;
        const int bn  = (rem & 3) * 128;
        const int kbase = kz * (Hd / KSPLIT);  // 128

        const int rA0 = tid >> 2;
        const int rA1 = rA0 + 64;
        const int kc  = tid & 3;
        const unsigned sOff0 = SWZ((unsigned)(rA0 * 64 + kc * 16));
        const unsigned sOff1 = SWZ((unsigned)(rA1 * 64 + kc * 16));

        float acc[4][4][4];
        #pragma unroll
        for (int i = 0; i < 4; i++)
            #pragma unroll
            for (int j = 0; j < 4; j++)
                #pragma unroll
                for (int q = 0; q < 4; q++) acc[i][j][q] = 0.0f;

        #define LOADL(I, BUF) do {                                            \
            int k0_ = kbase + (I) * 32;                                       \
            unsigned s_ = sbase + (BUF) * STAGE_G;                            \
            size_t a0_ = (size_t)(bm + rA0) * KC + Od + k0_ + kc * 8;         \
            size_t a1_ = (size_t)(bm + rA1) * KC + Od + k0_ + kc * 8;         \
            size_t b0_ = (size_t)(bn + rA0) * Hd + k0_ + kc * 8;              \
            size_t b1_ = (size_t)(bn + rA1) * Hd + k0_ + kc * 8;              \
            CP_ASYNC16(s_ + sOff0,          g_Xh  + a0_);                     \
            CP_ASYNC16(s_ + sOff1,          g_Xh  + a1_);                     \
            CP_ASYNC16(s_ + 8192  + sOff0,  g_Xl  + a0_);                     \
            CP_ASYNC16(s_ + 8192  + sOff1,  g_Xl  + a1_);                     \
            CP_ASYNC16(s_ + 16384 + sOff0,  g_Woh + b0_);                     \
            CP_ASYNC16(s_ + 16384 + sOff1,  g_Woh + b1_);                     \
            CP_ASYNC16(s_ + 24576 + sOff0,  g_Wol + b0_);                     \
            CP_ASYNC16(s_ + 24576 + sOff1,  g_Wol + b1_);                     \
            CP_COMMIT;                                                        \
        } while (0)

        LOADL(0, 0);
        LOADL(1, 1);

        for (int it = 0; it < NT_L; it++) {
            const int buf = it % 3;
            if (it + 2 < NT_L) {
                LOADL(it + 2, (it + 2) % 3);
                CP_WAIT2;
            } else if (it + 1 < NT_L) {
                CP_WAIT1;
            } else {
                CP_WAIT0;
            }
            __syncthreads();

            const unsigned sb = sbase + buf * STAGE_G;

            #pragma unroll
            for (int kk = 0; kk < 2; kk++) {
                const unsigned ar  = (unsigned)(lane & 15);
                const unsigned ahk = (unsigned)(lane >> 4);
                unsigned ah[4][4], al[4][4];
                #pragma unroll
                for (int mf = 0; mf < 4; mf++) {
                    unsigned byte = (warp_m * 64 + mf * 16 + ar) * 64 + kk * 32 + ahk * 16;
                    unsigned sw = SWZ(byte);
                    LDSM_X4(ah[mf][0], ah[mf][1], ah[mf][2], ah[mf][3], sb + sw);
                    LDSM_X4(al[mf][0], al[mf][1], al[mf][2], al[mf][3], sb + 8192 + sw);
                }
                unsigned bh[4][2], bl[4][2];
                #pragma unroll
                for (int pr = 0; pr < 2; pr++) {
                    unsigned n = warp_n * 32 + pr * 16 + (lane & 7) + ((lane >> 4) & 1) * 8;
                    unsigned byte = n * 64 + kk * 32 + ((lane >> 3) & 1) * 16;
                    unsigned sw = SWZ(byte);
                    unsigned r0, r1, r2, r3;
                    LDSM_X4(r0, r1, r2, r3, sb + 16384 + sw);
                    bh[2 * pr][0] = r0;      bh[2 * pr][1] = r1;
                    bh[2 * pr + 1][0] = r2;  bh[2 * pr + 1][1] = r3;
                    LDSM_X4(r0, r1, r2, r3, sb + 24576 + sw);
                    bl[2 * pr][0] = r0;      bl[2 * pr][1] = r1;
                    bl[2 * pr + 1][0] = r2;  bl[2 * pr + 1][1] = r3;
                }
                #pragma unroll
                for (int mf = 0; mf < 4; mf++)
                    #pragma unroll
                    for (int nf = 0; nf < 4; nf++)
                        MMA_BF16(acc[mf][nf], ah[mf], bh[nf]);
                #pragma unroll
                for (int mf = 0; mf < 4; mf++)
                    #pragma unroll
                    for (int nf = 0; nf < 4; nf++)
                        MMA_BF16(acc[mf][nf], ah[mf], bl[nf]);
                #pragma unroll
                for (int mf = 0; mf < 4; mf++)
                    #pragma unroll
                    for (int nf = 0; nf < 4; nf++)
                        MMA_BF16(acc[mf][nf], al[mf], bh[nf]);
            }
            __syncthreads();
        }

        float* lp = g_lp[kz];
        #pragma unroll
        for (int mf = 0; mf < 4; mf++) {
            #pragma unroll
            for (int nf = 0; nf < 4; nf++) {
                int row = bm + warp_m * 64 + mf * 16 + (lane >> 2);
                int col = bn + warp_n * 32 + nf * 8 + (lane & 3) * 2;
                *(float2*)&lp[(size_t)row * Od + col] = make_float2(acc[mf][nf][0], acc[mf][nf][1]);
                *(float2*)&lp[(size_t)(row + 8) * Od + col] = make_float2(acc[mf][nf][2], acc[mf][nf][3]);
            }
        }
    }
}

// ==========================================================================
// softmax + feedback (sums KSPLIT partials)
// ==========================================================================
#define RB 4

__global__ __launch_bounds__(256) void softmax_fb(const float* __restrict__ b_out,
                                                  float* __restrict__ out,
                                                  int step_off) {
    __shared__ float red[RB][8];

    const int b0 = blockIdx.x * RB;
    const int tid = threadIdx.x;
    const int warp = tid >> 5, lane = tid & 31;

    const int c0 = tid;
    const int c1 = tid + 256;
    const float bo0 = b_out[c0];
    const float bo1 = b_out[c1];

    float acc0[RB], acc1[RB];
    #pragma unroll
    for (int r = 0; r < RB; r++) {
        size_t i0 = (size_t)(b0 + r) * Od + c0;
        size_t i1 = (size_t)(b0 + r) * Od + c1;
        float s0 = bo0, s1 = bo1;
        #pragma unroll
        for (int z = 0; z < KSPLIT; z++) {
            s0 += g_lp[z][i0];
            s1 += g_lp[z][i1];
        }
        acc0[r] = s0;
        acc1[r] = s1;
    }

    #pragma unroll
    for (int r = 0; r < RB; r++) {
        float mm = fmaxf(acc0[r], acc1[r]);
        #pragma unroll
        for (int o = 16; o; o >>= 1) mm = fmaxf(mm, __shfl_xor_sync(0xffffffffu, mm, o));
        if (lane == 0) red[r][warp] = mm;
    }
    __syncthreads();
    float m[RB];
    #pragma unroll
    for (int r = 0; r < RB; r++) {
        float mm = red[r][0];
        #pragma unroll
        for (int w = 1; w < 8; w++) mm = fmaxf(mm, red[r][w]);
        m[r] = mm;
    }
    __syncthreads();

    #pragma unroll
    for (int r = 0; r < RB; r++) {
        acc0[r] = __expf(acc0[r] - m[r]);
        acc1[r] = __expf(acc1[r] - m[r]);
        float ss = acc0[r] + acc1[r];
        #pragma unroll
        for (int o = 16; o; o >>= 1) ss += __shfl_xor_sync(0xffffffffu, ss, o);
        if (lane == 0) red[r][warp] = ss;
    }
    __syncthreads();

    #pragma unroll
    for (int r = 0; r < RB; r++) {
        float ss = 0.0f;
        #pragma unroll
        for (int w = 0; w < 8; w++) ss += red[r][w];
        float inv = 1.0f / ss;
        float y0 = acc0[r] * inv;
        float y1 = acc1[r] * inv;
        int b = b0 + r;
        out[step_off + b * Od + c0] = y0;
        out[step_off + b * Od + c1] = y1;
        __nv_bfloat16 hi, lo;
        split_bf16(y0, hi, lo);
        g_Xh[b * KC + c0] = hi;  g_Xl[b * KC + c0] = lo;
        split_bf16(y1, hi, lo);
        g_Xh[b * KC + c1] = hi;  g_Xl[b * KC + c1] = lo;
    }
}

// ---------------- launcher ------------------------------------------------
extern "C" void kernel_launch(void* const* d_in, const int* in_sizes, int n_in,
                              void* d_out, int out_size) {
    const float* h0    = (const float*)d_in[0];
    const float* c0    = (const float*)d_in[1];
    const float* W_ih  = (const float*)d_in[2];
    const float* W_hh  = (const float*)d_in[3];
    const float* b_ih  = (const float*)d_in[4];
    const float* b_hh  = (const float*)d_in[5];
    const float* W_out = (const float*)d_in[6];
    const float* b_out = (const float*)d_in[7];
    float* out = (float*)d_out;

    const int T = out_size / (Bsz * Od);

    cudaFuncSetAttribute(gates_mma, cudaFuncAttributeMaxDynamicSharedMemorySize, SMEM_G);
    cudaFuncSetAttribute(mid_step,  cudaFuncAttributeMaxDynamicSharedMemorySize, SMEM_G);

    prep_weights<<<(G4 * KC + 255) / 256, 256>>>(W_ih, W_hh, b_ih, b_hh, W_out);
    prep_state<<<(Bsz * Hd + 255) / 256, 256>>>(h0, c0);

    dim3 ggrid(G4 / 128, Bsz / 128, GSPLIT);  // (32, 4, 2) = 256 blocks
    for (int t = 0; t < T; t++) {
        gates_mma<<<ggrid, 256, SMEM_G>>>();
        mid_step<<<128, 256, SMEM_G>>>();
        softmax_fb<<<Bsz / RB, 256>>>(b_out, out, (T - 1 - t) * Bsz * Od);
    }
}

// round 14
// speedup vs baseline: 1.1023x; 1.1023x over previous
#include <cuda_runtime.h>
#include <cuda_bf16.h>
#include <math.h>

#define Bsz 512
#define Hd  1024
#define Od  512
#define KC  1536   // Od + Hd
#define G4  4096   // 4*Hd
#define KSPLIT 8   // logits split-K
#define GSPLIT 2   // gates split-K

// ---------------- scratch ----------------
__device__ __nv_bfloat16 g_Xh[Bsz * KC];      // [B][KC]: x cols 0..511, h cols 512..1535
__device__ __nv_bfloat16 g_Xl[Bsz * KC];
__device__ __nv_bfloat16 g_Wh[G4 * KC];       // gate-interleaved [4j+gate][k]
__device__ __nv_bfloat16 g_Wl[G4 * KC];
__device__ __nv_bfloat16 g_Woh[Od * Hd];
__device__ __nv_bfloat16 g_Wol[Od * Hd];
__device__ float g_c[Bsz * Hd];               // [b][j]
__device__ float g_bias[G4];                  // gate-interleaved
__device__ float g_gp[GSPLIT][Bsz * G4];      // gates split-K partials
__device__ float g_lp[KSPLIT][Bsz * Od];      // logits split-K partials

// ---------------- grid barrier (two-level; ONLY in the 128-block kernel) --
struct GBar { unsigned sub[16]; unsigned root; unsigned gen; };
__device__ GBar g_barB;                       // zero-init; counters return to 0 each use

template<int PER_SUB>
__device__ __forceinline__ void gridbar(GBar* B, int bid) {
    __syncthreads();
    if (threadIdx.x == 0) {
        volatile unsigned* genp = &B->gen;
        unsigned mygen = *genp;               // read BEFORE arriving
        __threadfence();                      // release this block's writes
        int s = bid & 15;
        if (atomicAdd(&B->sub[s], 1u) == (unsigned)(PER_SUB - 1)) {
            B->sub[s] = 0u;                   // reset for next use
            if (atomicAdd(&B->root, 1u) == 15u) {
                B->root = 0u;
                __threadfence();
                atomicAdd(&B->gen, 1u);       // release
            }
        }
        while (*genp == mygen) { __nanosleep(32); }
        __threadfence();                      // acquire peers' writes
    }
    __syncthreads();
}

__device__ __forceinline__ void split_bf16(float v, __nv_bfloat16& hi, __nv_bfloat16& lo) {
    hi = __float2bfloat16(v);
    lo = __float2bfloat16(v - __bfloat162float(hi));
}
__device__ __forceinline__ float sigm(float x) { return 1.0f / (1.0f + __expf(-x)); }
__device__ __forceinline__ float ftanh(float x) { return 1.0f - 2.0f / (__expf(2.0f * x) + 1.0f); }

// ---------------- prep -------------------
__global__ void prep_weights(const float* __restrict__ W_ih,
                             const float* __restrict__ W_hh,
                             const float* __restrict__ b_ih,
                             const float* __restrict__ b_hh,
                             const float* __restrict__ W_out) {
    int idx = blockIdx.x * blockDim.x + threadIdx.x;
    if (idx < G4 * KC) {
        int r = idx / KC;
        int k = idx - r * KC;
        int j = r >> 2, gate = r & 3;
        int orow = gate * Hd + j;
        float w = (k < Od) ? W_ih[orow * Od + k] : W_hh[orow * Hd + (k - Od)];
        __nv_bfloat16 hi, lo;
        split_bf16(w, hi, lo);
        g_Wh[idx] = hi;
        g_Wl[idx] = lo;
    }
    if (idx < G4) {
        int j = idx >> 2, gate = idx & 3;
        g_bias[idx] = b_ih[gate * Hd + j] + b_hh[gate * Hd + j];
    }
    if (idx < Od * Hd) {
        __nv_bfloat16 hi, lo;
        split_bf16(W_out[idx], hi, lo);
        g_Woh[idx] = hi;
        g_Wol[idx] = lo;
    }
}

__global__ void prep_state(const float* __restrict__ h0,
                           const float* __restrict__ c0) {
    int idx = blockIdx.x * blockDim.x + threadIdx.x;
    if (idx < Bsz * Hd) {
        int b = idx >> 10;
        int j = idx & (Hd - 1);
        __nv_bfloat16 hi, lo;
        split_bf16(h0[idx], hi, lo);
        g_Xh[b * KC + Od + j] = hi;
        g_Xl[b * KC + Od + j] = lo;
        g_c[idx] = c0[idx];
    }
    if (idx < Bsz * Od) {
        int b = idx >> 9;
        int k = idx & (Od - 1);
        g_Xh[b * KC + k] = __float2bfloat16(0.0f);
        g_Xl[b * KC + k] = __float2bfloat16(0.0f);
    }
}

// ---------------- asm helpers --------------------------------------------
#define SWZ(b) ((b) ^ (((b) >> 3) & 0x30))   // 64B-row XOR swizzle

#define CP_ASYNC16(dst, src) asm volatile("cp.async.cg.shared.global [%0], [%1], 16;\n" :: "r"(dst), "l"(src))
#define CP_COMMIT            asm volatile("cp.async.commit_group;\n")
#define CP_WAIT2             asm volatile("cp.async.wait_group 2;\n")
#define CP_WAIT1             asm volatile("cp.async.wait_group 1;\n")
#define CP_WAIT0             asm volatile("cp.async.wait_group 0;\n")

#define LDSM_X4(d0, d1, d2, d3, addr) \
    asm volatile("ldmatrix.sync.aligned.m8n8.x4.shared.b16 {%0,%1,%2,%3}, [%4];" \
                 : "=r"(d0), "=r"(d1), "=r"(d2), "=r"(d3) : "r"(addr))

#define MMA_BF16(acc, a, b) \
    asm volatile( \
        "mma.sync.aligned.m16n8k16.row.col.f32.bf16.bf16.f32 " \
        "{%0,%1,%2,%3}, {%4,%5,%6,%7}, {%8,%9}, {%0,%1,%2,%3};" \
        : "+f"((acc)[0]), "+f"((acc)[1]), "+f"((acc)[2]), "+f"((acc)[3]) \
        : "r"((a)[0]), "r"((a)[1]), "r"((a)[2]), "r"((a)[3]), \
          "r"((b)[0]), "r"((b)[1]))

#define STAGE_G 32768
#define SMEM_G  (3 * STAGE_G)    // 96 KB

// ==========================================================================
// gates GEMM, split-K=2: partial[kz][512,4096] = X[:,kz*768:+768] @ W^T.
// BM=BN=128, BK=32, 24 k-iters. grid (32, 4, 2) = 256 blocks, 2 CTAs/SM.
// Partials only (cell update happens in cell_fuse).
// ==========================================================================
#define NT_G 24
#define KHALF 768

__global__ __launch_bounds__(256, 2) void gates_mma() {
    extern __shared__ __align__(1024) unsigned char smg[];

    const int tid  = threadIdx.x;
    const int wid  = tid >> 5;
    const int lane = tid & 31;
    const int warp_m = wid >> 2;   // 0..1
    const int warp_n = wid & 3;    // 0..3
    const int bm = blockIdx.y * 128;
    const int bn = blockIdx.x * 128;
    const int kz = blockIdx.z;
    const int kb = kz * KHALF;

    const unsigned sbase = (unsigned)__cvta_generic_to_shared(smg);

    const int rA0 = tid >> 2;        // 0..63
    const int rA1 = rA0 + 64;
    const int kc  = tid & 3;
    const unsigned sOff0 = SWZ((unsigned)(rA0 * 64 + kc * 16));
    const unsigned sOff1 = SWZ((unsigned)(rA1 * 64 + kc * 16));

    float acc[4][4][4];
    #pragma unroll
    for (int i = 0; i < 4; i++)
        #pragma unroll
        for (int j = 0; j < 4; j++)
            #pragma unroll
            for (int q = 0; q < 4; q++) acc[i][j][q] = 0.0f;

    #define LOADG(I, BUF) do {                                                \
        int k0_ = kb + (I) * 32;                                              \
        unsigned s_ = sbase + (BUF) * STAGE_G;                                \
        size_t a0_ = (size_t)(bm + rA0) * KC + k0_ + kc * 8;                  \
        size_t a1_ = (size_t)(bm + rA1) * KC + k0_ + kc * 8;                  \
        size_t b0_ = (size_t)(bn + rA0) * KC + k0_ + kc * 8;                  \
        size_t b1_ = (size_t)(bn + rA1) * KC + k0_ + kc * 8;                  \
        CP_ASYNC16(s_ + sOff0,          g_Xh + a0_);                          \
        CP_ASYNC16(s_ + sOff1,          g_Xh + a1_);                          \
        CP_ASYNC16(s_ + 8192  + sOff0,  g_Xl + a0_);                          \
        CP_ASYNC16(s_ + 8192  + sOff1,  g_Xl + a1_);                          \
        CP_ASYNC16(s_ + 16384 + sOff0,  g_Wh + b0_);                          \
        CP_ASYNC16(s_ + 16384 + sOff1,  g_Wh + b1_);                          \
        CP_ASYNC16(s_ + 24576 + sOff0,  g_Wl + b0_);                          \
        CP_ASYNC16(s_ + 24576 + sOff1,  g_Wl + b1_);                          \
        CP_COMMIT;                                                            \
    } while (0)

    LOADG(0, 0);
    LOADG(1, 1);

    for (int it = 0; it < NT_G; it++) {
        const int buf = it % 3;
        if (it + 2 < NT_G) {
            LOADG(it + 2, (it + 2) % 3);
            CP_WAIT2;
        } else if (it + 1 < NT_G) {
            CP_WAIT1;
        } else {
            CP_WAIT0;
        }
        __syncthreads();

        const unsigned sb = sbase + buf * STAGE_G;

        #pragma unroll
        for (int kk = 0; kk < 2; kk++) {
            const unsigned ar  = (unsigned)(lane & 15);
            const unsigned ahk = (unsigned)(lane >> 4);
            unsigned ah[4][4], al[4][4];
            #pragma unroll
            for (int mf = 0; mf < 4; mf++) {
                unsigned byte = (warp_m * 64 + mf * 16 + ar) * 64 + kk * 32 + ahk * 16;
                unsigned sw = SWZ(byte);
                LDSM_X4(ah[mf][0], ah[mf][1], ah[mf][2], ah[mf][3], sb + sw);
                LDSM_X4(al[mf][0], al[mf][1], al[mf][2], al[mf][3], sb + 8192 + sw);
            }
            unsigned bh[4][2], bl[4][2];
            #pragma unroll
            for (int pr = 0; pr < 2; pr++) {
                unsigned n = warp_n * 32 + pr * 16 + (lane & 7) + ((lane >> 4) & 1) * 8;
                unsigned byte = n * 64 + kk * 32 + ((lane >> 3) & 1) * 16;
                unsigned sw = SWZ(byte);
                unsigned r0, r1, r2, r3;
                LDSM_X4(r0, r1, r2, r3, sb + 16384 + sw);
                bh[2 * pr][0] = r0;      bh[2 * pr][1] = r1;
                bh[2 * pr + 1][0] = r2;  bh[2 * pr + 1][1] = r3;
                LDSM_X4(r0, r1, r2, r3, sb + 24576 + sw);
                bl[2 * pr][0] = r0;      bl[2 * pr][1] = r1;
                bl[2 * pr + 1][0] = r2;  bl[2 * pr + 1][1] = r3;
            }
            #pragma unroll
            for (int mf = 0; mf < 4; mf++)
                #pragma unroll
                for (int nf = 0; nf < 4; nf++)
                    MMA_BF16(acc[mf][nf], ah[mf], bh[nf]);
            #pragma unroll
            for (int mf = 0; mf < 4; mf++)
                #pragma unroll
                for (int nf = 0; nf < 4; nf++)
                    MMA_BF16(acc[mf][nf], ah[mf], bl[nf]);
            #pragma unroll
            for (int mf = 0; mf < 4; mf++)
                #pragma unroll
                for (int nf = 0; nf < 4; nf++)
                    MMA_BF16(acc[mf][nf], al[mf], bh[nf]);
        }
        __syncthreads();
    }

    float* gp = g_gp[kz];
    #pragma unroll
    for (int mf = 0; mf < 4; mf++) {
        #pragma unroll
        for (int nf = 0; nf < 4; nf++) {
            int row = bm + warp_m * 64 + mf * 16 + (lane >> 2);
            int col = bn + warp_n * 32 + nf * 8 + (lane & 3) * 2;
            *(float2*)&gp[(size_t)row * G4 + col] = make_float2(acc[mf][nf][0], acc[mf][nf][1]);
            *(float2*)&gp[(size_t)(row + 8) * G4 + col] = make_float2(acc[mf][nf][2], acc[mf][nf][3]);
        }
    }
}

// ==========================================================================
// cell_fuse (2048 blocks -> full-grid bandwidth): sum partials + bias,
// LSTM cell update, write h (bf16 split). One thread per (b, j).
// ==========================================================================
__global__ __launch_bounds__(256) void cell_fuse() {
    int idx = blockIdx.x * blockDim.x + threadIdx.x;   // Bsz*Hd threads
    int b = idx >> 10;
    int j = idx & (Hd - 1);

    float4 p0 = *(const float4*)&g_gp[0][(size_t)b * G4 + 4 * j];
    float4 p1 = *(const float4*)&g_gp[1][(size_t)b * G4 + 4 * j];
    float4 bs = *(const float4*)&g_bias[4 * j];

    float gi = p0.x + p1.x + bs.x;
    float gf = p0.y + p1.y + bs.y;
    float gg = p0.z + p1.z + bs.z;
    float go = p0.w + p1.w + bs.w;

    float c  = g_c[idx];
    float cn = sigm(gf) * c + sigm(gi) * ftanh(gg);
    g_c[idx] = cn;
    float hn = sigm(go) * ftanh(cn);

    __nv_bfloat16 hi, lo;
    split_bf16(hn, hi, lo);
    g_Xh[b * KC + Od + j] = hi;
    g_Xl[b * KC + Od + j] = lo;
}

// ==========================================================================
// logits_sm (128 blocks): logits split-K=8 (NT=4 pipelined) -> g_lp,
// gridbar, then softmax + feedback (4 rows per block).
// ==========================================================================
#define NT_L 4
#define RB 4

__global__ __launch_bounds__(256, 2) void logits_sm(const float* __restrict__ b_out,
                                                    float* __restrict__ out,
                                                    int step_off) {
    extern __shared__ __align__(1024) unsigned char sml[];
    const unsigned sbase = (unsigned)__cvta_generic_to_shared(sml);
    const int bid  = blockIdx.x;
    const int tid  = threadIdx.x;
    const int wid  = tid >> 5;
    const int lane = tid & 31;
    const int warp_m = wid >> 2;
    const int warp_n = wid & 3;

    // ---- phase L: logits GEMM split-K=8 ----
    {
        const int kz  = bid >> 4;              // 0..7
        const int rem = bid & 15;
        const int bm  = (rem >> 2) * 128;
        const int bn  = (rem & 3) * 128;
        const int kbase = kz * (Hd / KSPLIT);  // 128

        const int rA0 = tid >> 2;
        const int rA1 = rA0 + 64;
        const int kc  = tid & 3;
        const unsigned sOff0 = SWZ((unsigned)(rA0 * 64 + kc * 16));
        const unsigned sOff1 = SWZ((unsigned)(rA1 * 64 + kc * 16));

        float acc[4][4][4];
        #pragma unroll
        for (int i = 0; i < 4; i++)
            #pragma unroll
            for (int j = 0; j < 4; j++)
                #pragma unroll
                for (int q = 0; q < 4; q++) acc[i][j][q] = 0.0f;

        #define LOADL(I, BUF) do {                                            \
            int k0_ = kbase + (I) * 32;                                       \
            unsigned s_ = sbase + (BUF) * STAGE_G;                            \
            size_t a0_ = (size_t)(bm + rA0) * KC + Od + k0_ + kc * 8;         \
            size_t a1_ = (size_t)(bm + rA1) * KC + Od + k0_ + kc * 8;         \
            size_t b0_ = (size_t)(bn + rA0) * Hd + k0_ + kc * 8;              \
            size_t b1_ = (size_t)(bn + rA1) * Hd + k0_ + kc * 8;              \
            CP_ASYNC16(s_ + sOff0,          g_Xh  + a0_);                     \
            CP_ASYNC16(s_ + sOff1,          g_Xh  + a1_);                     \
            CP_ASYNC16(s_ + 8192  + sOff0,  g_Xl  + a0_);                     \
            CP_ASYNC16(s_ + 8192  + sOff1,  g_Xl  + a1_);                     \
            CP_ASYNC16(s_ + 16384 + sOff0,  g_Woh + b0_);                     \
            CP_ASYNC16(s_ + 16384 + sOff1,  g_Woh + b1_);                     \
            CP_ASYNC16(s_ + 24576 + sOff0,  g_Wol + b0_);                     \
            CP_ASYNC16(s_ + 24576 + sOff1,  g_Wol + b1_);                     \
            CP_COMMIT;                                                        \
        } while (0)

        LOADL(0, 0);
        LOADL(1, 1);

        for (int it = 0; it < NT_L; it++) {
            const int buf = it % 3;
            if (it + 2 < NT_L) {
                LOADL(it + 2, (it + 2) % 3);
                CP_WAIT2;
            } else if (it + 1 < NT_L) {
                CP_WAIT1;
            } else {
                CP_WAIT0;
            }
            __syncthreads();

            const unsigned sb = sbase + buf * STAGE_G;

            #pragma unroll
            for (int kk = 0; kk < 2; kk++) {
                const unsigned ar  = (unsigned)(lane & 15);
                const unsigned ahk = (unsigned)(lane >> 4);
                unsigned ah[4][4], al[4][4];
                #pragma unroll
                for (int mf = 0; mf < 4; mf++) {
                    unsigned byte = (warp_m * 64 + mf * 16 + ar) * 64 + kk * 32 + ahk * 16;
                    unsigned sw = SWZ(byte);
                    LDSM_X4(ah[mf][0], ah[mf][1], ah[mf][2], ah[mf][3], sb + sw);
                    LDSM_X4(al[mf][0], al[mf][1], al[mf][2], al[mf][3], sb + 8192 + sw);
                }
                unsigned bh[4][2], bl[4][2];
                #pragma unroll
                for (int pr = 0; pr < 2; pr++) {
                    unsigned n = warp_n * 32 + pr * 16 + (lane & 7) + ((lane >> 4) & 1) * 8;
                    unsigned byte = n * 64 + kk * 32 + ((lane >> 3) & 1) * 16;
                    unsigned sw = SWZ(byte);
                    unsigned r0, r1, r2, r3;
                    LDSM_X4(r0, r1, r2, r3, sb + 16384 + sw);
                    bh[2 * pr][0] = r0;      bh[2 * pr][1] = r1;
                    bh[2 * pr + 1][0] = r2;  bh[2 * pr + 1][1] = r3;
                    LDSM_X4(r0, r1, r2, r3, sb + 24576 + sw);
                    bl[2 * pr][0] = r0;      bl[2 * pr][1] = r1;
                    bl[2 * pr + 1][0] = r2;  bl[2 * pr + 1][1] = r3;
                }
                #pragma unroll
                for (int mf = 0; mf < 4; mf++)
                    #pragma unroll
                    for (int nf = 0; nf < 4; nf++)
                        MMA_BF16(acc[mf][nf], ah[mf], bh[nf]);
                #pragma unroll
                for (int mf = 0; mf < 4; mf++)
                    #pragma unroll
                    for (int nf = 0; nf < 4; nf++)
                        MMA_BF16(acc[mf][nf], ah[mf], bl[nf]);
                #pragma unroll
                for (int mf = 0; mf < 4; mf++)
                    #pragma unroll
                    for (int nf = 0; nf < 4; nf++)
                        MMA_BF16(acc[mf][nf], al[mf], bh[nf]);
            }
            __syncthreads();
        }

        float* lp = g_lp[kz];
        #pragma unroll
        for (int mf = 0; mf < 4; mf++) {
            #pragma unroll
            for (int nf = 0; nf < 4; nf++) {
                int row = bm + warp_m * 64 + mf * 16 + (lane >> 2);
                int col = bn + warp_n * 32 + nf * 8 + (lane & 3) * 2;
                *(float2*)&lp[(size_t)row * Od + col] = make_float2(acc[mf][nf][0], acc[mf][nf][1]);
                *(float2*)&lp[(size_t)(row + 8) * Od + col] = make_float2(acc[mf][nf][2], acc[mf][nf][3]);
            }
        }
    }
    gridbar<8>(&g_barB, bid);                  // 128 blocks: 16 subgroups x 8

    // ---- phase S: softmax + feedback (4 rows per block) ----
    {
        float (*red)[8] = (float (*)[8])sml;   // reuse dynamic smem
        const int b0 = bid * RB;
        const int warp = tid >> 5;

        const int c0 = tid;
        const int c1 = tid + 256;
        const float bo0 = b_out[c0];
        const float bo1 = b_out[c1];

        float acc0[RB], acc1[RB];
        #pragma unroll
        for (int r = 0; r < RB; r++) {
            size_t i0 = (size_t)(b0 + r) * Od + c0;
            size_t i1 = (size_t)(b0 + r) * Od + c1;
            float s0 = bo0, s1 = bo1;
            #pragma unroll
            for (int z = 0; z < KSPLIT; z++) {
                s0 += g_lp[z][i0];
                s1 += g_lp[z][i1];
            }
            acc0[r] = s0;
            acc1[r] = s1;
        }

        #pragma unroll
        for (int r = 0; r < RB; r++) {
            float mm = fmaxf(acc0[r], acc1[r]);
            #pragma unroll
            for (int o = 16; o; o >>= 1) mm = fmaxf(mm, __shfl_xor_sync(0xffffffffu, mm, o));
            if (lane == 0) red[r][warp] = mm;
        }
        __syncthreads();
        float m[RB];
        #pragma unroll
        for (int r = 0; r < RB; r++) {
            float mm = red[r][0];
            #pragma unroll
            for (int w = 1; w < 8; w++) mm = fmaxf(mm, red[r][w]);
            m[r] = mm;
        }
        __syncthreads();

        #pragma unroll
        for (int r = 0; r < RB; r++) {
            acc0[r] = __expf(acc0[r] - m[r]);
            acc1[r] = __expf(acc1[r] - m[r]);
            float ss = acc0[r] + acc1[r];
            #pragma unroll
            for (int o = 16; o; o >>= 1) ss += __shfl_xor_sync(0xffffffffu, ss, o);
            if (lane == 0) red[r][warp] = ss;
        }
        __syncthreads();

        #pragma unroll
        for (int r = 0; r < RB; r++) {
            float ss = 0.0f;
            #pragma unroll
            for (int w = 0; w < 8; w++) ss += red[r][w];
            float inv = 1.0f / ss;
            float y0 = acc0[r] * inv;
            float y1 = acc1[r] * inv;
            int b = b0 + r;
            out[step_off + b * Od + c0] = y0;
            out[step_off + b * Od + c1] = y1;
            __nv_bfloat16 hi, lo;
            split_bf16(y0, hi, lo);
            g_Xh[b * KC + c0] = hi;  g_Xl[b * KC + c0] = lo;
            split_bf16(y1, hi, lo);
            g_Xh[b * KC + c1] = hi;  g_Xl[b * KC + c1] = lo;
        }
    }
}

// ---------------- launcher ------------------------------------------------
extern "C" void kernel_launch(void* const* d_in, const int* in_sizes, int n_in,
                              void* d_out, int out_size) {
    const float* h0    = (const float*)d_in[0];
    const float* c0    = (const float*)d_in[1];
    const float* W_ih  = (const float*)d_in[2];
    const float* W_hh  = (const float*)d_in[3];
    const float* b_ih  = (const float*)d_in[4];
    const float* b_hh  = (const float*)d_in[5];
    const float* W_out = (const float*)d_in[6];
    const float* b_out = (const float*)d_in[7];
    float* out = (float*)d_out;

    const int T = out_size / (Bsz * Od);

    cudaFuncSetAttribute(gates_mma, cudaFuncAttributeMaxDynamicSharedMemorySize, SMEM_G);
    cudaFuncSetAttribute(logits_sm, cudaFuncAttributeMaxDynamicSharedMemorySize, SMEM_G);

    prep_weights<<<(G4 * KC + 255) / 256, 256>>>(W_ih, W_hh, b_ih, b_hh, W_out);
    prep_state<<<(Bsz * Hd + 255) / 256, 256>>>(h0, c0);

    dim3 ggrid(G4 / 128, Bsz / 128, GSPLIT);  // (32, 4, 2) = 256 blocks
    for (int t = 0; t < T; t++) {
        gates_mma<<<ggrid, 256, SMEM_G>>>();
        cell_fuse<<<(Bsz * Hd) / 256, 256>>>();
        logits_sm<<<128, 256, SMEM_G>>>(b_out, out, (T - 1 - t) * Bsz * Od);
    }
}

// round 15
// speedup vs baseline: 1.4843x; 1.3466x over previous
#include <cuda_runtime.h>
#include <cuda_fp16.h>
#include <math.h>

#define Bsz 512
#define Hd  1024
#define Od  512
#define KC  1536   // Od + Hd
#define G4  4096   // 4*Hd
#define KSPLIT 8   // logits split-K
#define GSPLIT 2   // gates split-K

// ---------------- scratch ----------------
// X stored as single fp16 (truncation error ~2^-11, random per step).
// Weights stored as fp16 hi+lo (fully corrected -> no systematic bias).
__device__ __half g_X[Bsz * KC];              // [B][KC]: x cols 0..511, h cols 512..1535
__device__ __half g_Wh[G4 * KC];              // gate-interleaved [4j+gate][k] hi
__device__ __half g_Wl[G4 * KC];              // lo
__device__ __half g_Woh[Od * Hd];
__device__ __half g_Wol[Od * Hd];
__device__ float g_c[Bsz * Hd];               // [b][j]
__device__ float g_bias[G4];                  // gate-interleaved
__device__ float g_gp[GSPLIT][Bsz * G4];      // gates split-K partials
__device__ float g_lp[KSPLIT][Bsz * Od];      // logits split-K partials

// ---------------- grid barrier (two-level; ONLY in the 128-block kernel) --
struct GBar { unsigned sub[16]; unsigned root; unsigned gen; };
__device__ GBar g_barB;                       // zero-init; counters return to 0 each use

template<int PER_SUB>
__device__ __forceinline__ void gridbar(GBar* B, int bid) {
    __syncthreads();
    if (threadIdx.x == 0) {
        volatile unsigned* genp = &B->gen;
        unsigned mygen = *genp;               // read BEFORE arriving
        __threadfence();                      // release this block's writes
        int s = bid & 15;
        if (atomicAdd(&B->sub[s], 1u) == (unsigned)(PER_SUB - 1)) {
            B->sub[s] = 0u;                   // reset for next use
            if (atomicAdd(&B->root, 1u) == 15u) {
                B->root = 0u;
                __threadfence();
                atomicAdd(&B->gen, 1u);       // release
            }
        }
        while (*genp == mygen) { __nanosleep(32); }
        __threadfence();                      // acquire peers' writes
    }
    __syncthreads();
}

__device__ __forceinline__ void split_f16(float v, __half& hi, __half& lo) {
    hi = __float2half(v);
    lo = __float2half(v - __half2float(hi));
}
__device__ __forceinline__ float sigm(float x) { return 1.0f / (1.0f + __expf(-x)); }
__device__ __forceinline__ float ftanh(float x) { return 1.0f - 2.0f / (__expf(2.0f * x) + 1.0f); }

// ---------------- prep -------------------
__global__ void prep_weights(const float* __restrict__ W_ih,
                             const float* __restrict__ W_hh,
                             const float* __restrict__ b_ih,
                             const float* __restrict__ b_hh,
                             const float* __restrict__ W_out) {
    int idx = blockIdx.x * blockDim.x + threadIdx.x;
    if (idx < G4 * KC) {
        int r = idx / KC;
        int k = idx - r * KC;
        int j = r >> 2, gate = r & 3;
        int orow = gate * Hd + j;
        float w = (k < Od) ? W_ih[orow * Od + k] : W_hh[orow * Hd + (k - Od)];
        __half hi, lo;
        split_f16(w, hi, lo);
        g_Wh[idx] = hi;
        g_Wl[idx] = lo;
    }
    if (idx < G4) {
        int j = idx >> 2, gate = idx & 3;
        g_bias[idx] = b_ih[gate * Hd + j] + b_hh[gate * Hd + j];
    }
    if (idx < Od * Hd) {
        __half hi, lo;
        split_f16(W_out[idx], hi, lo);
        g_Woh[idx] = hi;
        g_Wol[idx] = lo;
    }
}

__global__ void prep_state(const float* __restrict__ h0,
                           const float* __restrict__ c0) {
    int idx = blockIdx.x * blockDim.x + threadIdx.x;
    if (idx < Bsz * Hd) {
        int b = idx >> 10;
        int j = idx & (Hd - 1);
        g_X[b * KC + Od + j] = __float2half(h0[idx]);
        g_c[idx] = c0[idx];
    }
    if (idx < Bsz * Od) {
        int b = idx >> 9;
        int k = idx & (Od - 1);
        g_X[b * KC + k] = __float2half(0.0f);
    }
}

// ---------------- asm helpers --------------------------------------------
#define SWZ(b) ((b) ^ (((b) >> 3) & 0x30))   // 64B-row XOR swizzle

#define CP_ASYNC16(dst, src) asm volatile("cp.async.cg.shared.global [%0], [%1], 16;\n" :: "r"(dst), "l"(src))
#define CP_COMMIT            asm volatile("cp.async.commit_group;\n")
#define CP_WAIT2             asm volatile("cp.async.wait_group 2;\n")
#define CP_WAIT1             asm volatile("cp.async.wait_group 1;\n")
#define CP_WAIT0             asm volatile("cp.async.wait_group 0;\n")

#define LDSM_X4(d0, d1, d2, d3, addr) \
    asm volatile("ldmatrix.sync.aligned.m8n8.x4.shared.b16 {%0,%1,%2,%3}, [%4];" \
                 : "=r"(d0), "=r"(d1), "=r"(d2), "=r"(d3) : "r"(addr))

#define MMA_F16(acc, a, b) \
    asm volatile( \
        "mma.sync.aligned.m16n8k16.row.col.f32.f16.f16.f32 " \
        "{%0,%1,%2,%3}, {%4,%5,%6,%7}, {%8,%9}, {%0,%1,%2,%3};" \
        : "+f"((acc)[0]), "+f"((acc)[1]), "+f"((acc)[2]), "+f"((acc)[3]) \
        : "r"((a)[0]), "r"((a)[1]), "r"((a)[2]), "r"((a)[3]), \
          "r"((b)[0]), "r"((b)[1]))

#define STAGE_G 24576                 // A 8K | Bh 8K | Bl 8K
#define SMEM_G  (3 * STAGE_G)         // 72 KB

// ==========================================================================
// gates GEMM, split-K=2: partial[kz][512,4096] = X[:,kz*768:+768] @ W^T.
// fp16 2-product: Xh·Wh + Xh·Wl, fp32 accumulate.
// BM=BN=128, BK=32, 24 k-iters. grid (32, 4, 2) = 256 blocks, 2 CTAs/SM.
// ==========================================================================
#define NT_G 24
#define KHALF 768

__global__ __launch_bounds__(256, 2) void gates_mma() {
    extern __shared__ __align__(1024) unsigned char smg[];

    const int tid  = threadIdx.x;
    const int wid  = tid >> 5;
    const int lane = tid & 31;
    const int warp_m = wid >> 2;   // 0..1
    const int warp_n = wid & 3;    // 0..3
    const int bm = blockIdx.y * 128;
    const int bn = blockIdx.x * 128;
    const int kz = blockIdx.z;
    const int kb = kz * KHALF;

    const unsigned sbase = (unsigned)__cvta_generic_to_shared(smg);

    const int rA0 = tid >> 2;        // 0..63
    const int rA1 = rA0 + 64;
    const int kc  = tid & 3;
    const unsigned sOff0 = SWZ((unsigned)(rA0 * 64 + kc * 16));
    const unsigned sOff1 = SWZ((unsigned)(rA1 * 64 + kc * 16));

    float acc[4][4][4];
    #pragma unroll
    for (int i = 0; i < 4; i++)
        #pragma unroll
        for (int j = 0; j < 4; j++)
            #pragma unroll
            for (int q = 0; q < 4; q++) acc[i][j][q] = 0.0f;

    #define LOADG(I, BUF) do {                                                \
        int k0_ = kb + (I) * 32;                                              \
        unsigned s_ = sbase + (BUF) * STAGE_G;                                \
        size_t a0_ = (size_t)(bm + rA0) * KC + k0_ + kc * 8;                  \
        size_t a1_ = (size_t)(bm + rA1) * KC + k0_ + kc * 8;                  \
        size_t b0_ = (size_t)(bn + rA0) * KC + k0_ + kc * 8;                  \
        size_t b1_ = (size_t)(bn + rA1) * KC + k0_ + kc * 8;                  \
        CP_ASYNC16(s_ + sOff0,          g_X  + a0_);                          \
        CP_ASYNC16(s_ + sOff1,          g_X  + a1_);                          \
        CP_ASYNC16(s_ + 8192  + sOff0,  g_Wh + b0_);                          \
        CP_ASYNC16(s_ + 8192  + sOff1,  g_Wh + b1_);                          \
        CP_ASYNC16(s_ + 16384 + sOff0,  g_Wl + b0_);                          \
        CP_ASYNC16(s_ + 16384 + sOff1,  g_Wl + b1_);                          \
        CP_COMMIT;                                                            \
    } while (0)

    LOADG(0, 0);
    LOADG(1, 1);

    for (int it = 0; it < NT_G; it++) {
        const int buf = it % 3;
        if (it + 2 < NT_G) {
            LOADG(it + 2, (it + 2) % 3);
            CP_WAIT2;
        } else if (it + 1 < NT_G) {
            CP_WAIT1;
        } else {
            CP_WAIT0;
        }
        __syncthreads();

        const unsigned sb = sbase + buf * STAGE_G;

        #pragma unroll
        for (int kk = 0; kk < 2; kk++) {
            const unsigned ar  = (unsigned)(lane & 15);
            const unsigned ahk = (unsigned)(lane >> 4);
            unsigned a_[4][4];
            #pragma unroll
            for (int mf = 0; mf < 4; mf++) {
                unsigned byte = (warp_m * 64 + mf * 16 + ar) * 64 + kk * 32 + ahk * 16;
                unsigned sw = SWZ(byte);
                LDSM_X4(a_[mf][0], a_[mf][1], a_[mf][2], a_[mf][3], sb + sw);
            }
            unsigned bh[4][2], bl[4][2];
            #pragma unroll
            for (int pr = 0; pr < 2; pr++) {
                unsigned n = warp_n * 32 + pr * 16 + (lane & 7) + ((lane >> 4) & 1) * 8;
                unsigned byte = n * 64 + kk * 32 + ((lane >> 3) & 1) * 16;
                unsigned sw = SWZ(byte);
                unsigned r0, r1, r2, r3;
                LDSM_X4(r0, r1, r2, r3, sb + 8192 + sw);
                bh[2 * pr][0] = r0;      bh[2 * pr][1] = r1;
                bh[2 * pr + 1][0] = r2;  bh[2 * pr + 1][1] = r3;
                LDSM_X4(r0, r1, r2, r3, sb + 16384 + sw);
                bl[2 * pr][0] = r0;      bl[2 * pr][1] = r1;
                bl[2 * pr + 1][0] = r2;  bl[2 * pr + 1][1] = r3;
            }
            #pragma unroll
            for (int mf = 0; mf < 4; mf++)
                #pragma unroll
                for (int nf = 0; nf < 4; nf++)
                    MMA_F16(acc[mf][nf], a_[mf], bh[nf]);
            #pragma unroll
            for (int mf = 0; mf < 4; mf++)
                #pragma unroll
                for (int nf = 0; nf < 4; nf++)
                    MMA_F16(acc[mf][nf], a_[mf], bl[nf]);
        }
        __syncthreads();
    }

    float* gp = g_gp[kz];
    #pragma unroll
    for (int mf = 0; mf < 4; mf++) {
        #pragma unroll
        for (int nf = 0; nf < 4; nf++) {
            int row = bm + warp_m * 64 + mf * 16 + (lane >> 2);
            int col = bn + warp_n * 32 + nf * 8 + (lane & 3) * 2;
            *(float2*)&gp[(size_t)row * G4 + col] = make_float2(acc[mf][nf][0], acc[mf][nf][1]);
            *(float2*)&gp[(size_t)(row + 8) * G4 + col] = make_float2(acc[mf][nf][2], acc[mf][nf][3]);
        }
    }
}

// ==========================================================================
// cell_fuse (2048 blocks): sum partials + bias, LSTM cell, write h (fp16).
// ==========================================================================
__global__ __launch_bounds__(256) void cell_fuse() {
    int idx = blockIdx.x * blockDim.x + threadIdx.x;   // Bsz*Hd threads
    int b = idx >> 10;
    int j = idx & (Hd - 1);

    float4 p0 = *(const float4*)&g_gp[0][(size_t)b * G4 + 4 * j];
    float4 p1 = *(const float4*)&g_gp[1][(size_t)b * G4 + 4 * j];
    float4 bs = *(const float4*)&g_bias[4 * j];

    float gi = p0.x + p1.x + bs.x;
    float gf = p0.y + p1.y + bs.y;
    float gg = p0.z + p1.z + bs.z;
    float go = p0.w + p1.w + bs.w;

    float c  = g_c[idx];
    float cn = sigm(gf) * c + sigm(gi) * ftanh(gg);
    g_c[idx] = cn;
    float hn = sigm(go) * ftanh(cn);

    g_X[b * KC + Od + j] = __float2half(hn);
}

// ==========================================================================
// logits_sm (128 blocks): logits split-K=8 (NT=4, fp16 2-product) -> g_lp,
// gridbar, then softmax + feedback (4 rows per block).
// ==========================================================================
#define NT_L 4
#define RB 4

__global__ __launch_bounds__(256, 2) void logits_sm(const float* __restrict__ b_out,
                                                    float* __restrict__ out,
                                                    int step_off) {
    extern __shared__ __align__(1024) unsigned char sml[];
    const unsigned sbase = (unsigned)__cvta_generic_to_shared(sml);
    const int bid  = blockIdx.x;
    const int tid  = threadIdx.x;
    const int wid  = tid >> 5;
    const int lane = tid & 31;
    const int warp_m = wid >> 2;
    const int warp_n = wid & 3;

    // ---- phase L: logits GEMM split-K=8 ----
    {
        const int kz  = bid >> 4;              // 0..7
        const int rem = bid & 15;
        const int bm  = (rem >> 2) * 128;
        const int bn  = (rem & 3) * 128;
        const int kbase = kz * (Hd / KSPLIT);  // 128

        const int rA0 = tid >> 2;
        const int rA1 = rA0 + 64;
        const int kc  = tid & 3;
        const unsigned sOff0 = SWZ((unsigned)(rA0 * 64 + kc * 16));
        const unsigned sOff1 = SWZ((unsigned)(rA1 * 64 + kc * 16));

        float acc[4][4][4];
        #pragma unroll
        for (int i = 0; i < 4; i++)
            #pragma unroll
            for (int j = 0; j < 4; j++)
                #pragma unroll
                for (int q = 0; q < 4; q++) acc[i][j][q] = 0.0f;

        #define LOADL(I, BUF) do {                                            \
            int k0_ = kbase + (I) * 32;                                       \
            unsigned s_ = sbase + (BUF) * STAGE_G;                            \
            size_t a0_ = (size_t)(bm + rA0) * KC + Od + k0_ + kc * 8;         \
            size_t a1_ = (size_t)(bm + rA1) * KC + Od + k0_ + kc * 8;         \
            size_t b0_ = (size_t)(bn + rA0) * Hd + k0_ + kc * 8;              \
            size_t b1_ = (size_t)(bn + rA1) * Hd + k0_ + kc * 8;              \
            CP_ASYNC16(s_ + sOff0,          g_X   + a0_);                     \
            CP_ASYNC16(s_ + sOff1,          g_X   + a1_);                     \
            CP_ASYNC16(s_ + 8192  + sOff0,  g_Woh + b0_);                     \
            CP_ASYNC16(s_ + 8192  + sOff1,  g_Woh + b1_);                     \
            CP_ASYNC16(s_ + 16384 + sOff0,  g_Wol + b0_);                     \
            CP_ASYNC16(s_ + 16384 + sOff1,  g_Wol + b1_);                     \
            CP_COMMIT;                                                        \
        } while (0)

        LOADL(0, 0);
        LOADL(1, 1);

        for (int it = 0; it < NT_L; it++) {
            const int buf = it % 3;
            if (it + 2 < NT_L) {
                LOADL(it + 2, (it + 2) % 3);
                CP_WAIT2;
            } else if (it + 1 < NT_L) {
                CP_WAIT1;
            } else {
                CP_WAIT0;
            }
            __syncthreads();

            const unsigned sb = sbase + buf * STAGE_G;

            #pragma unroll
            for (int kk = 0; kk < 2; kk++) {
                const unsigned ar  = (unsigned)(lane & 15);
                const unsigned ahk = (unsigned)(lane >> 4);
                unsigned a_[4][4];
                #pragma unroll
                for (int mf = 0; mf < 4; mf++) {
                    unsigned byte = (warp_m * 64 + mf * 16 + ar) * 64 + kk * 32 + ahk * 16;
                    unsigned sw = SWZ(byte);
                    LDSM_X4(a_[mf][0], a_[mf][1], a_[mf][2], a_[mf][3], sb + sw);
                }
                unsigned bh[4][2], bl[4][2];
                #pragma unroll
                for (int pr = 0; pr < 2; pr++) {
                    unsigned n = warp_n * 32 + pr * 16 + (lane & 7) + ((lane >> 4) & 1) * 8;
                    unsigned byte = n * 64 + kk * 32 + ((lane >> 3) & 1) * 16;
                    unsigned sw = SWZ(byte);
                    unsigned r0, r1, r2, r3;
                    LDSM_X4(r0, r1, r2, r3, sb + 8192 + sw);
                    bh[2 * pr][0] = r0;      bh[2 * pr][1] = r1;
                    bh[2 * pr + 1][0] = r2;  bh[2 * pr + 1][1] = r3;
                    LDSM_X4(r0, r1, r2, r3, sb + 16384 + sw);
                    bl[2 * pr][0] = r0;      bl[2 * pr][1] = r1;
                    bl[2 * pr + 1][0] = r2;  bl[2 * pr + 1][1] = r3;
                }
                #pragma unroll
                for (int mf = 0; mf < 4; mf++)
                    #pragma unroll
                    for (int nf = 0; nf < 4; nf++)
                        MMA_F16(acc[mf][nf], a_[mf], bh[nf]);
                #pragma unroll
                for (int mf = 0; mf < 4; mf++)
                    #pragma unroll
                    for (int nf = 0; nf < 4; nf++)
                        MMA_F16(acc[mf][nf], a_[mf], bl[nf]);
            }
            __syncthreads();
        }

        float* lp = g_lp[kz];
        #pragma unroll
        for (int mf = 0; mf < 4; mf++) {
            #pragma unroll
            for (int nf = 0; nf < 4; nf++) {
                int row = bm + warp_m * 64 + mf * 16 + (lane >> 2);
                int col = bn + warp_n * 32 + nf * 8 + (lane & 3) * 2;
                *(float2*)&lp[(size_t)row * Od + col] = make_float2(acc[mf][nf][0], acc[mf][nf][1]);
                *(float2*)&lp[(size_t)(row + 8) * Od + col] = make_float2(acc[mf][nf][2], acc[mf][nf][3]);
            }
        }
    }
    gridbar<8>(&g_barB, bid);                  // 128 blocks: 16 subgroups x 8

    // ---- phase S: softmax + feedback (4 rows per block) ----
    {
        float (*red)[8] = (float (*)[8])sml;   // reuse dynamic smem
        const int b0 = bid * RB;
        const int warp = tid >> 5;

        const int c0 = tid;
        const int c1 = tid + 256;
        const float bo0 = b_out[c0];
        const float bo1 = b_out[c1];

        float acc0[RB], acc1[RB];
        #pragma unroll
        for (int r = 0; r < RB; r++) {
            size_t i0 = (size_t)(b0 + r) * Od + c0;
            size_t i1 = (size_t)(b0 + r) * Od + c1;
            float s0 = bo0, s1 = bo1;
            #pragma unroll
            for (int z = 0; z < KSPLIT; z++) {
                s0 += g_lp[z][i0];
                s1 += g_lp[z][i1];
            }
            acc0[r] = s0;
            acc1[r] = s1;
        }

        #pragma unroll
        for (int r = 0; r < RB; r++) {
            float mm = fmaxf(acc0[r], acc1[r]);
            #pragma unroll
            for (int o = 16; o; o >>= 1) mm = fmaxf(mm, __shfl_xor_sync(0xffffffffu, mm, o));
            if (lane == 0) red[r][warp] = mm;
        }
        __syncthreads();
        float m[RB];
        #pragma unroll
        for (int r = 0; r < RB; r++) {
            float mm = red[r][0];
            #pragma unroll
            for (int w = 1; w < 8; w++) mm = fmaxf(mm, red[r][w]);
            m[r] = mm;
        }
        __syncthreads();

        #pragma unroll
        for (int r = 0; r < RB; r++) {
            acc0[r] = __expf(acc0[r] - m[r]);
            acc1[r] = __expf(acc1[r] - m[r]);
            float ss = acc0[r] + acc1[r];
            #pragma unroll
            for (int o = 16; o; o >>= 1) ss += __shfl_xor_sync(0xffffffffu, ss, o);
            if (lane == 0) red[r][warp] = ss;
        }
        __syncthreads();

        #pragma unroll
        for (int r = 0; r < RB; r++) {
            float ss = 0.0f;
            #pragma unroll
            for (int w = 0; w < 8; w++) ss += red[r][w];
            float inv = 1.0f / ss;
            float y0 = acc0[r] * inv;
            float y1 = acc1[r] * inv;
            int b = b0 + r;
            out[step_off + b * Od + c0] = y0;
            out[step_off + b * Od + c1] = y1;
            g_X[b * KC + c0] = __float2half(y0);
            g_X[b * KC + c1] = __float2half(y1);
        }
    }
}

// ---------------- launcher ------------------------------------------------
extern "C" void kernel_launch(void* const* d_in, const int* in_sizes, int n_in,
                              void* d_out, int out_size) {
    const float* h0    = (const float*)d_in[0];
    const float* c0    = (const float*)d_in[1];
    const float* W_ih  = (const float*)d_in[2];
    const float* W_hh  = (const float*)d_in[3];
    const float* b_ih  = (const float*)d_in[4];
    const float* b_hh  = (const float*)d_in[5];
    const float* W_out = (const float*)d_in[6];
    const float* b_out = (const float*)d_in[7];
    float* out = (float*)d_out;

    const int T = out_size / (Bsz * Od);

    cudaFuncSetAttribute(gates_mma, cudaFuncAttributeMaxDynamicSharedMemorySize, SMEM_G);
    cudaFuncSetAttribute(logits_sm, cudaFuncAttributeMaxDynamicSharedMemorySize, SMEM_G);

    prep_weights<<<(G4 * KC + 255) / 256, 256>>>(W_ih, W_hh, b_ih, b_hh, W_out);
    prep_state<<<(Bsz * Hd + 255) / 256, 256>>>(h0, c0);

    dim3 ggrid(G4 / 128, Bsz / 128, GSPLIT);  // (32, 4, 2) = 256 blocks
    for (int t = 0; t < T; t++) {
        gates_mma<<<ggrid, 256, SMEM_G>>>();
        cell_fuse<<<(Bsz * Hd) / 256, 256>>>();
        logits_sm<<<128, 256, SMEM_G>>>(b_out, out, (T - 1 - t) * Bsz * Od);
    }
}

// round 16
// speedup vs baseline: 2.0746x; 1.3977x over previous
#include <cuda_runtime.h>
#include <cuda_fp16.h>
#include <math.h>

#define Bsz 512
#define Hd  1024
#define Od  512
#define KC  1536   // Od + Hd
#define G4  4096   // 4*Hd
#define KSPLIT 8   // logits split-K
#define GSPLIT 2   // gates split-K

// ---------------- scratch ----------------
// X and W both stored as single fp16; fp32 accumulate in HMMA.
__device__ __half g_X[Bsz * KC];              // [B][KC]: x cols 0..511, h cols 512..1535
__device__ __half g_W[G4 * KC];               // gate-interleaved [4j+gate][k]
__device__ __half g_Wo[Od * Hd];
__device__ float g_c[Bsz * Hd];               // [b][j]
__device__ float g_bias[G4];                  // gate-interleaved
__device__ float g_gp[GSPLIT][Bsz * G4];      // gates split-K partials
__device__ float g_lp[KSPLIT][Bsz * Od];      // logits split-K partials

// ---------------- grid barrier (two-level; ONLY in the 128-block kernel) --
struct GBar { unsigned sub[16]; unsigned root; unsigned gen; };
__device__ GBar g_barB;                       // zero-init; counters return to 0 each use

template<int PER_SUB>
__device__ __forceinline__ void gridbar(GBar* B, int bid) {
    __syncthreads();
    if (threadIdx.x == 0) {
        volatile unsigned* genp = &B->gen;
        unsigned mygen = *genp;               // read BEFORE arriving
        __threadfence();                      // release this block's writes
        int s = bid & 15;
        if (atomicAdd(&B->sub[s], 1u) == (unsigned)(PER_SUB - 1)) {
            B->sub[s] = 0u;                   // reset for next use
            if (atomicAdd(&B->root, 1u) == 15u) {
                B->root = 0u;
                __threadfence();
                atomicAdd(&B->gen, 1u);       // release
            }
        }
        while (*genp == mygen) { __nanosleep(32); }
        __threadfence();                      // acquire peers' writes
    }
    __syncthreads();
}

__device__ __forceinline__ float sigm(float x) { return 1.0f / (1.0f + __expf(-x)); }
__device__ __forceinline__ float ftanh(float x) { return 1.0f - 2.0f / (__expf(2.0f * x) + 1.0f); }

// ---------------- prep -------------------
__global__ void prep_weights(const float* __restrict__ W_ih,
                             const float* __restrict__ W_hh,
                             const float* __restrict__ b_ih,
                             const float* __restrict__ b_hh,
                             const float* __restrict__ W_out) {
    int idx = blockIdx.x * blockDim.x + threadIdx.x;
    if (idx < G4 * KC) {
        int r = idx / KC;
        int k = idx - r * KC;
        int j = r >> 2, gate = r & 3;
        int orow = gate * Hd + j;
        float w = (k < Od) ? W_ih[orow * Od + k] : W_hh[orow * Hd + (k - Od)];
        g_W[idx] = __float2half(w);
    }
    if (idx < G4) {
        int j = idx >> 2, gate = idx & 3;
        g_bias[idx] = b_ih[gate * Hd + j] + b_hh[gate * Hd + j];
    }
    if (idx < Od * Hd) {
        g_Wo[idx] = __float2half(W_out[idx]);
    }
}

__global__ void prep_state(const float* __restrict__ h0,
                           const float* __restrict__ c0) {
    int idx = blockIdx.x * blockDim.x + threadIdx.x;
    if (idx < Bsz * Hd) {
        int b = idx >> 10;
        int j = idx & (Hd - 1);
        g_X[b * KC + Od + j] = __float2half(h0[idx]);
        g_c[idx] = c0[idx];
    }
    if (idx < Bsz * Od) {
        int b = idx >> 9;
        int k = idx & (Od - 1);
        g_X[b * KC + k] = __float2half(0.0f);
    }
}

// ---------------- asm helpers --------------------------------------------
#define SWZ(b) ((b) ^ (((b) >> 3) & 0x30))   // 64B-row XOR swizzle

#define CP_ASYNC16(dst, src) asm volatile("cp.async.cg.shared.global [%0], [%1], 16;\n" :: "r"(dst), "l"(src))
#define CP_COMMIT            asm volatile("cp.async.commit_group;\n")
#define CP_WAIT2             asm volatile("cp.async.wait_group 2;\n")
#define CP_WAIT1             asm volatile("cp.async.wait_group 1;\n")
#define CP_WAIT0             asm volatile("cp.async.wait_group 0;\n")

#define LDSM_X4(d0, d1, d2, d3, addr) \
    asm volatile("ldmatrix.sync.aligned.m8n8.x4.shared.b16 {%0,%1,%2,%3}, [%4];" \
                 : "=r"(d0), "=r"(d1), "=r"(d2), "=r"(d3) : "r"(addr))

#define MMA_F16(acc, a, b) \
    asm volatile( \
        "mma.sync.aligned.m16n8k16.row.col.f32.f16.f16.f32 " \
        "{%0,%1,%2,%3}, {%4,%5,%6,%7}, {%8,%9}, {%0,%1,%2,%3};" \
        : "+f"((acc)[0]), "+f"((acc)[1]), "+f"((acc)[2]), "+f"((acc)[3]) \
        : "r"((a)[0]), "r"((a)[1]), "r"((a)[2]), "r"((a)[3]), \
          "r"((b)[0]), "r"((b)[1]))

#define STAGE_G 16384                 // A 8K | B 8K
#define SMEM_G  (3 * STAGE_G)         // 48 KB

// ==========================================================================
// gates GEMM, split-K=2: partial[kz][512,4096] = X[:,kz*768:+768] @ W^T.
// single fp16 product, fp32 accumulate.
// BM=BN=128, BK=32, 24 k-iters. grid (32, 4, 2) = 256 blocks, 2 CTAs/SM.
// ==========================================================================
#define NT_G 24
#define KHALF 768

__global__ __launch_bounds__(256, 2) void gates_mma() {
    extern __shared__ __align__(1024) unsigned char smg[];

    const int tid  = threadIdx.x;
    const int wid  = tid >> 5;
    const int lane = tid & 31;
    const int warp_m = wid >> 2;   // 0..1
    const int warp_n = wid & 3;    // 0..3
    const int bm = blockIdx.y * 128;
    const int bn = blockIdx.x * 128;
    const int kz = blockIdx.z;
    const int kb = kz * KHALF;

    const unsigned sbase = (unsigned)__cvta_generic_to_shared(smg);

    const int rA0 = tid >> 2;        // 0..63
    const int rA1 = rA0 + 64;
    const int kc  = tid & 3;
    const unsigned sOff0 = SWZ((unsigned)(rA0 * 64 + kc * 16));
    const unsigned sOff1 = SWZ((unsigned)(rA1 * 64 + kc * 16));

    float acc[4][4][4];
    #pragma unroll
    for (int i = 0; i < 4; i++)
        #pragma unroll
        for (int j = 0; j < 4; j++)
            #pragma unroll
            for (int q = 0; q < 4; q++) acc[i][j][q] = 0.0f;

    #define LOADG(I, BUF) do {                                                \
        int k0_ = kb + (I) * 32;                                              \
        unsigned s_ = sbase + (BUF) * STAGE_G;                                \
        size_t a0_ = (size_t)(bm + rA0) * KC + k0_ + kc * 8;                  \
        size_t a1_ = (size_t)(bm + rA1) * KC + k0_ + kc * 8;                  \
        size_t b0_ = (size_t)(bn + rA0) * KC + k0_ + kc * 8;                  \
        size_t b1_ = (size_t)(bn + rA1) * KC + k0_ + kc * 8;                  \
        CP_ASYNC16(s_ + sOff0,          g_X + a0_);                           \
        CP_ASYNC16(s_ + sOff1,          g_X + a1_);                           \
        CP_ASYNC16(s_ + 8192 + sOff0,   g_W + b0_);                           \
        CP_ASYNC16(s_ + 8192 + sOff1,   g_W + b1_);                           \
        CP_COMMIT;                                                            \
    } while (0)

    LOADG(0, 0);
    LOADG(1, 1);

    for (int it = 0; it < NT_G; it++) {
        const int buf = it % 3;
        if (it + 2 < NT_G) {
            LOADG(it + 2, (it + 2) % 3);
            CP_WAIT2;
        } else if (it + 1 < NT_G) {
            CP_WAIT1;
        } else {
            CP_WAIT0;
        }
        __syncthreads();

        const unsigned sb = sbase + buf * STAGE_G;

        #pragma unroll
        for (int kk = 0; kk < 2; kk++) {
            const unsigned ar  = (unsigned)(lane & 15);
            const unsigned ahk = (unsigned)(lane >> 4);
            unsigned a_[4][4];
            #pragma unroll
            for (int mf = 0; mf < 4; mf++) {
                unsigned byte = (warp_m * 64 + mf * 16 + ar) * 64 + kk * 32 + ahk * 16;
                unsigned sw = SWZ(byte);
                LDSM_X4(a_[mf][0], a_[mf][1], a_[mf][2], a_[mf][3], sb + sw);
            }
            unsigned b_[4][2];
            #pragma unroll
            for (int pr = 0; pr < 2; pr++) {
                unsigned n = warp_n * 32 + pr * 16 + (lane & 7) + ((lane >> 4) & 1) * 8;
                unsigned byte = n * 64 + kk * 32 + ((lane >> 3) & 1) * 16;
                unsigned sw = SWZ(byte);
                unsigned r0, r1, r2, r3;
                LDSM_X4(r0, r1, r2, r3, sb + 8192 + sw);
                b_[2 * pr][0] = r0;      b_[2 * pr][1] = r1;
                b_[2 * pr + 1][0] = r2;  b_[2 * pr + 1][1] = r3;
            }
            #pragma unroll
            for (int mf = 0; mf < 4; mf++)
                #pragma unroll
                for (int nf = 0; nf < 4; nf++)
                    MMA_F16(acc[mf][nf], a_[mf], b_[nf]);
        }
        __syncthreads();
    }

    float* gp = g_gp[kz];
    #pragma unroll
    for (int mf = 0; mf < 4; mf++) {
        #pragma unroll
        for (int nf = 0; nf < 4; nf++) {
            int row = bm + warp_m * 64 + mf * 16 + (lane >> 2);
            int col = bn + warp_n * 32 + nf * 8 + (lane & 3) * 2;
            *(float2*)&gp[(size_t)row * G4 + col] = make_float2(acc[mf][nf][0], acc[mf][nf][1]);
            *(float2*)&gp[(size_t)(row + 8) * G4 + col] = make_float2(acc[mf][nf][2], acc[mf][nf][3]);
        }
    }
}

// ==========================================================================
// cell_fuse (2048 blocks): sum partials + bias, LSTM cell, write h (fp16).
// ==========================================================================
__global__ __launch_bounds__(256) void cell_fuse() {
    int idx = blockIdx.x * blockDim.x + threadIdx.x;   // Bsz*Hd threads
    int b = idx >> 10;
    int j = idx & (Hd - 1);

    float4 p0 = *(const float4*)&g_gp[0][(size_t)b * G4 + 4 * j];
    float4 p1 = *(const float4*)&g_gp[1][(size_t)b * G4 + 4 * j];
    float4 bs = *(const float4*)&g_bias[4 * j];

    float gi = p0.x + p1.x + bs.x;
    float gf = p0.y + p1.y + bs.y;
    float gg = p0.z + p1.z + bs.z;
    float go = p0.w + p1.w + bs.w;

    float c  = g_c[idx];
    float cn = sigm(gf) * c + sigm(gi) * ftanh(gg);
    g_c[idx] = cn;
    float hn = sigm(go) * ftanh(cn);

    g_X[b * KC + Od + j] = __float2half(hn);
}

// ==========================================================================
// logits_sm (128 blocks): logits split-K=8 (NT=4, single fp16 product),
// gridbar, then softmax + feedback (4 rows per block).
// ==========================================================================
#define NT_L 4
#define RB 4

__global__ __launch_bounds__(256, 2) void logits_sm(const float* __restrict__ b_out,
                                                    float* __restrict__ out,
                                                    int step_off) {
    extern __shared__ __align__(1024) unsigned char sml[];
    const unsigned sbase = (unsigned)__cvta_generic_to_shared(sml);
    const int bid  = blockIdx.x;
    const int tid  = threadIdx.x;
    const int wid  = tid >> 5;
    const int lane = tid & 31;
    const int warp_m = wid >> 2;
    const int warp_n = wid & 3;

    // ---- phase L: logits GEMM split-K=8 ----
    {
        const int kz  = bid >> 4;              // 0..7
        const int rem = bid & 15;
        const int bm  = (rem >> 2) * 128;
        const int bn  = (rem & 3) * 128;
        const int kbase = kz * (Hd / KSPLIT);  // 128

        const int rA0 = tid >> 2;
        const int rA1 = rA0 + 64;
        const int kc  = tid & 3;
        const unsigned sOff0 = SWZ((unsigned)(rA0 * 64 + kc * 16));
        const unsigned sOff1 = SWZ((unsigned)(rA1 * 64 + kc * 16));

        float acc[4][4][4];
        #pragma unroll
        for (int i = 0; i < 4; i++)
            #pragma unroll
            for (int j = 0; j < 4; j++)
                #pragma unroll
                for (int q = 0; q < 4; q++) acc[i][j][q] = 0.0f;

        #define LOADL(I, BUF) do {                                            \
            int k0_ = kbase + (I) * 32;                                       \
            unsigned s_ = sbase + (BUF) * STAGE_G;                            \
            size_t a0_ = (size_t)(bm + rA0) * KC + Od + k0_ + kc * 8;         \
            size_t a1_ = (size_t)(bm + rA1) * KC + Od + k0_ + kc * 8;         \
            size_t b0_ = (size_t)(bn + rA0) * Hd + k0_ + kc * 8;              \
            size_t b1_ = (size_t)(bn + rA1) * Hd + k0_ + kc * 8;              \
            CP_ASYNC16(s_ + sOff0,          g_X  + a0_);                      \
            CP_ASYNC16(s_ + sOff1,          g_X  + a1_);                      \
            CP_ASYNC16(s_ + 8192 + sOff0,   g_Wo + b0_);                      \
            CP_ASYNC16(s_ + 8192 + sOff1,   g_Wo + b1_);                      \
            CP_COMMIT;                                                        \
        } while (0)

        LOADL(0, 0);
        LOADL(1, 1);

        for (int it = 0; it < NT_L; it++) {
            const int buf = it % 3;
            if (it + 2 < NT_L) {
                LOADL(it + 2, (it + 2) % 3);
                CP_WAIT2;
            } else if (it + 1 < NT_L) {
                CP_WAIT1;
            } else {
                CP_WAIT0;
            }
            __syncthreads();

            const unsigned sb = sbase + buf * STAGE_G;

            #pragma unroll
            for (int kk = 0; kk < 2; kk++) {
                const unsigned ar  = (unsigned)(lane & 15);
                const unsigned ahk = (unsigned)(lane >> 4);
                unsigned a_[4][4];
                #pragma unroll
                for (int mf = 0; mf < 4; mf++) {
                    unsigned byte = (warp_m * 64 + mf * 16 + ar) * 64 + kk * 32 + ahk * 16;
                    unsigned sw = SWZ(byte);
                    LDSM_X4(a_[mf][0], a_[mf][1], a_[mf][2], a_[mf][3], sb + sw);
                }
                unsigned b_[4][2];
                #pragma unroll
                for (int pr = 0; pr < 2; pr++) {
                    unsigned n = warp_n * 32 + pr * 16 + (lane & 7) + ((lane >> 4) & 1) * 8;
                    unsigned byte = n * 64 + kk * 32 + ((lane >> 3) & 1) * 16;
                    unsigned sw = SWZ(byte);
                    unsigned r0, r1, r2, r3;
                    LDSM_X4(r0, r1, r2, r3, sb + 8192 + sw);
                    b_[2 * pr][0] = r0;      b_[2 * pr][1] = r1;
                    b_[2 * pr + 1][0] = r2;  b_[2 * pr + 1][1] = r3;
                }
                #pragma unroll
                for (int mf = 0; mf < 4; mf++)
                    #pragma unroll
                    for (int nf = 0; nf < 4; nf++)
                        MMA_F16(acc[mf][nf], a_[mf], b_[nf]);
            }
            __syncthreads();
        }

        float* lp = g_lp[kz];
        #pragma unroll
        for (int mf = 0; mf < 4; mf++) {
            #pragma unroll
            for (int nf = 0; nf < 4; nf++) {
                int row = bm + warp_m * 64 + mf * 16 + (lane >> 2);
                int col = bn + warp_n * 32 + nf * 8 + (lane & 3) * 2;
                *(float2*)&lp[(size_t)row * Od + col] = make_float2(acc[mf][nf][0], acc[mf][nf][1]);
                *(float2*)&lp[(size_t)(row + 8) * Od + col] = make_float2(acc[mf][nf][2], acc[mf][nf][3]);
            }
        }
    }
    gridbar<8>(&g_barB, bid);                  // 128 blocks: 16 subgroups x 8

    // ---- phase S: softmax + feedback (4 rows per block) ----
    {
        float (*red)[8] = (float (*)[8])sml;   // reuse dynamic smem
        const int b0 = bid * RB;
        const int warp = tid >> 5;

        const int c0 = tid;
        const int c1 = tid + 256;
        const float bo0 = b_out[c0];
        const float bo1 = b_out[c1];

        float acc0[RB], acc1[RB];
        #pragma unroll
        for (int r = 0; r < RB; r++) {
            size_t i0 = (size_t)(b0 + r) * Od + c0;
            size_t i1 = (size_t)(b0 + r) * Od + c1;
            float s0 = bo0, s1 = bo1;
            #pragma unroll
            for (int z = 0; z < KSPLIT; z++) {
                s0 += g_lp[z][i0];
                s1 += g_lp[z][i1];
            }
            acc0[r] = s0;
            acc1[r] = s1;
        }

        #pragma unroll
        for (int r = 0; r < RB; r++) {
            float mm = fmaxf(acc0[r], acc1[r]);
            #pragma unroll
            for (int o = 16; o; o >>= 1) mm = fmaxf(mm, __shfl_xor_sync(0xffffffffu, mm, o));
            if (lane == 0) red[r][warp] = mm;
        }
        __syncthreads();
        float m[RB];
        #pragma unroll
        for (int r = 0; r < RB; r++) {
            float mm = red[r][0];
            #pragma unroll
            for (int w = 1; w < 8; w++) mm = fmaxf(mm, red[r][w]);
            m[r] = mm;
        }
        __syncthreads();

        #pragma unroll
        for (int r = 0; r < RB; r++) {
            acc0[r] = __expf(acc0[r] - m[r]);
            acc1[r] = __expf(acc1[r] - m[r]);
            float ss = acc0[r] + acc1[r];
            #pragma unroll
            for (int o = 16; o; o >>= 1) ss += __shfl_xor_sync(0xffffffffu, ss, o);
            if (lane == 0) red[r][warp] = ss;
        }
        __syncthreads();

        #pragma unroll
        for (int r = 0; r < RB; r++) {
            float ss = 0.0f;
            #pragma unroll
            for (int w = 0; w < 8; w++) ss += red[r][w];
            float inv = 1.0f / ss;
            float y0 = acc0[r] * inv;
            float y1 = acc1[r] * inv;
            int b = b0 + r;
            out[step_off + b * Od + c0] = y0;
            out[step_off + b * Od + c1] = y1;
            g_X[b * KC + c0] = __float2half(y0);
            g_X[b * KC + c1] = __float2half(y1);
        }
    }
}

// ---------------- launcher ------------------------------------------------
extern "C" void kernel_launch(void* const* d_in, const int* in_sizes, int n_in,
                              void* d_out, int out_size) {
    const float* h0    = (const float*)d_in[0];
    const float* c0    = (const float*)d_in[1];
    const float* W_ih  = (const float*)d_in[2];
    const float* W_hh  = (const float*)d_in[3];
    const float* b_ih  = (const float*)d_in[4];
    const float* b_hh  = (const float*)d_in[5];
    const float* W_out = (const float*)d_in[6];
    const float* b_out = (const float*)d_in[7];
    float* out = (float*)d_out;

    const int T = out_size / (Bsz * Od);

    cudaFuncSetAttribute(gates_mma, cudaFuncAttributeMaxDynamicSharedMemorySize, SMEM_G);
    cudaFuncSetAttribute(logits_sm, cudaFuncAttributeMaxDynamicSharedMemorySize, SMEM_G);

    prep_weights<<<(G4 * KC + 255) / 256, 256>>>(W_ih, W_hh, b_ih, b_hh, W_out);
    prep_state<<<(Bsz * Hd + 255) / 256, 256>>>(h0, c0);

    dim3 ggrid(G4 / 128, Bsz / 128, GSPLIT);  // (32, 4, 2) = 256 blocks
    for (int t = 0; t < T; t++) {
        gates_mma<<<ggrid, 256, SMEM_G>>>();
        cell_fuse<<<(Bsz * Hd) / 256, 256>>>();
        logits_sm<<<128, 256, SMEM_G>>>(b_out, out, (T - 1 - t) * Bsz * Od);
    }
}